// round 16
// baseline (speedup 1.0000x reference)
#include <cuda_runtime.h>
#include <cuda_fp16.h>

#define N_NODES 50000
#define N_EDGES 1600000
#define IN_DIM 6
#define H 64
#define SCAN_BLOCKS ((N_NODES + 255) / 256)   // 196
#define NB 64                                  // nodes per k_node block
#define E4 (N_EDGES / 4)                       // 400000 int4s

// Scratch (device globals — zero-initialized at load; no runtime allocation)
__device__ int    g_deg     [N_NODES];        // reset to 0 by k_scan23 each replay
__device__ int    g_rowstart[N_NODES + 1];
__device__ int    g_cursor  [N_NODES];
__device__ int    g_adj     [N_EDGES];
__device__ int    g_bsum    [SCAN_BLOCKS];
__device__ __half g_uh      [N_NODES * H];    // u = z @ W2_l   (fp16, gather operand)
__device__ float  g_yr      [N_NODES * H];    // yr = z @ W2_r + b2_l

// ---- CSR build ----------------------------------------------------------

// Pure no-return reduction (REDG) — no scoreboard dependency, no pos traffic
__global__ void k_count(const int* __restrict__ ei) {
    int tid = blockIdx.x * blockDim.x + threadIdx.x;
    if (tid >= E4) return;
    const int4* dsts = reinterpret_cast<const int4*>(ei + N_EDGES);
    int4 d = __ldg(&dsts[tid]);
    atomicAdd(&g_deg[d.x], 1);
    atomicAdd(&g_deg[d.y], 1);
    atomicAdd(&g_deg[d.z], 1);
    atomicAdd(&g_deg[d.w], 1);
}

__device__ __forceinline__ int warp_incl_scan(int v, int lane) {
    #pragma unroll
    for (int o = 1; o < 32; o <<= 1) {
        int u = __shfl_up_sync(0xffffffffu, v, o);
        if (lane >= o) v += u;
    }
    return v;
}

__global__ void k_scan1() {
    __shared__ int ws[8];
    int t = threadIdx.x;
    int i = blockIdx.x * 256 + t;
    int val = (i < N_NODES) ? g_deg[i] : 0;
    int lane = t & 31, w = t >> 5;
    int v = warp_incl_scan(val, lane);
    if (lane == 31) ws[w] = v;
    __syncthreads();
    if (w == 0 && lane < 8) {
        int u = ws[lane];
        #pragma unroll
        for (int o = 1; o < 8; o <<= 1) {
            int p = __shfl_up_sync(0xffu, u, o);
            if (lane >= o) u += p;
        }
        ws[lane] = u;
    }
    __syncthreads();
    int excl = (v - val) + (w > 0 ? ws[w - 1] : 0);
    if (i < N_NODES) g_rowstart[i] = excl;
    if (t == 255) g_bsum[blockIdx.x] = excl + val;
}

// Phase 2+3 merged; also materializes the place-cursor and re-arms g_deg.
__global__ void k_scan23() {
    __shared__ int ws[8];
    __shared__ int incl[256];
    int t = threadIdx.x;
    int val = (t < SCAN_BLOCKS) ? g_bsum[t] : 0;
    int lane = t & 31, w = t >> 5;
    int v = warp_incl_scan(val, lane);
    if (lane == 31) ws[w] = v;
    __syncthreads();
    if (w == 0 && lane < 8) {
        int u = ws[lane];
        #pragma unroll
        for (int o = 1; o < 8; o <<= 1) {
            int p = __shfl_up_sync(0xffu, u, o);
            if (lane >= o) u += p;
        }
        ws[lane] = u;
    }
    __syncthreads();
    incl[t] = v + (w > 0 ? ws[w - 1] : 0);
    __syncthreads();
    int bid = blockIdx.x;
    int off = (bid > 0) ? incl[bid - 1] : 0;
    int i = bid * 256 + t;
    if (i < N_NODES) {
        int r = g_rowstart[i] + off;
        g_rowstart[i] = r;
        g_cursor[i]   = r;
        g_deg[i] = 0;
    }
    if (i == 0) g_rowstart[N_NODES] = N_EDGES;
}

// Cursor-atomic placement, 4 independent chains per thread
__global__ void k_place(const int* __restrict__ ei) {
    int tid = blockIdx.x * blockDim.x + threadIdx.x;
    if (tid >= E4) return;
    const int4* srcs = reinterpret_cast<const int4*>(ei);
    const int4* dsts = reinterpret_cast<const int4*>(ei + N_EDGES);
    int4 s = __ldg(&srcs[tid]);
    int4 d = __ldg(&dsts[tid]);
    int p0 = atomicAdd(&g_cursor[d.x], 1);
    int p1 = atomicAdd(&g_cursor[d.y], 1);
    int p2 = atomicAdd(&g_cursor[d.z], 1);
    int p3 = atomicAdd(&g_cursor[d.w], 1);
    g_adj[p0] = s.x;
    g_adj[p1] = s.y;
    g_adj[p2] = s.z;
    g_adj[p3] = s.w;
}

// ---- Fused node kernel (R13 proven) ----------------------------------------
__global__ void k_node(const float* __restrict__ x,
                       const float* __restrict__ W1l,
                       const float* __restrict__ b1l,
                       const float* __restrict__ W1r,
                       const float* __restrict__ W2l,
                       const float* __restrict__ b2l,
                       const float* __restrict__ W2r) {
    __shared__ __align__(16) float sW1l[IN_DIM * H];
    __shared__ __align__(16) float sW1r[IN_DIM * H];
    __shared__ __align__(16) float sb1[H];
    __shared__ __align__(16) float sW2l[H * H];
    __shared__ __align__(16) float sW2r[H * H];
    __shared__ __align__(16) float sb2[H];
    __shared__ __align__(16) float smean[NB * IN_DIM];
    __shared__ __align__(16) float sz[NB * H];
    int t = threadIdx.x;
    for (int i = t; i < IN_DIM * H; i += 256) { sW1l[i] = W1l[i]; sW1r[i] = W1r[i]; }
    for (int i = t; i < H * H; i += 256)      { sW2l[i] = W2l[i]; sW2r[i] = W2r[i]; }
    if (t < H) { sb1[t] = b1l[t]; sb2[t] = b2l[t]; }

    int base = blockIdx.x * NB;
    int w = t >> 5, lane = t & 31;

    #pragma unroll
    for (int i = 0; i < 8; i++) {
        int node = base + w * 8 + i;
        int ln = w * 8 + i;
        float a0 = 0, a1 = 0, a2 = 0, a3 = 0, a4 = 0, a5 = 0;
        int beg = 0, end = 0;
        if (node < N_NODES) {
            beg = g_rowstart[node];
            end = g_rowstart[node + 1];
            for (int p = beg + lane; p < end; p += 32) {
                int s = __ldg(&g_adj[p]);
                const float2* xs = reinterpret_cast<const float2*>(x + (size_t)s * IN_DIM);
                float2 u = __ldg(&xs[0]), q = __ldg(&xs[1]), r = __ldg(&xs[2]);
                a0 += u.x; a1 += u.y; a2 += q.x; a3 += q.y; a4 += r.x; a5 += r.y;
            }
        }
        #pragma unroll
        for (int o = 16; o > 0; o >>= 1) {
            a0 += __shfl_xor_sync(0xffffffffu, a0, o);
            a1 += __shfl_xor_sync(0xffffffffu, a1, o);
            a2 += __shfl_xor_sync(0xffffffffu, a2, o);
            a3 += __shfl_xor_sync(0xffffffffu, a3, o);
            a4 += __shfl_xor_sync(0xffffffffu, a4, o);
            a5 += __shfl_xor_sync(0xffffffffu, a5, o);
        }
        if (lane == 0 && node < N_NODES) {
            int deg = end - beg;
            float inv = (deg > 0) ? 1.0f / (float)deg : 0.0f;
            smean[ln * IN_DIM + 0] = a0 * inv;
            smean[ln * IN_DIM + 1] = a1 * inv;
            smean[ln * IN_DIM + 2] = a2 * inv;
            smean[ln * IN_DIM + 3] = a3 * inv;
            smean[ln * IN_DIM + 4] = a4 * inv;
            smean[ln * IN_DIM + 5] = a5 * inv;
        }
    }
    __syncthreads();

    int nq = t >> 4;
    int j4 = t & 15;
    int j0 = j4 * 4;
    int lnb = nq * 4;
    int nodeb = base + lnb;

    // Phase A
    {
        float4 acc[4];
        float4 b = *reinterpret_cast<const float4*>(&sb1[j0]);
        #pragma unroll
        for (int i = 0; i < 4; i++) acc[i] = b;
        #pragma unroll
        for (int k = 0; k < IN_DIM; k++) {
            float4 wl = *reinterpret_cast<const float4*>(&sW1l[k * H + j0]);
            float4 wr = *reinterpret_cast<const float4*>(&sW1r[k * H + j0]);
            #pragma unroll
            for (int i = 0; i < 4; i++) {
                int node = nodeb + i;
                float m = smean[(lnb + i) * IN_DIM + k];
                float xv = (node < N_NODES) ? __ldg(&x[(size_t)node * IN_DIM + k]) : 0.0f;
                acc[i].x += m * wl.x + xv * wr.x;
                acc[i].y += m * wl.y + xv * wr.y;
                acc[i].z += m * wl.z + xv * wr.z;
                acc[i].w += m * wl.w + xv * wr.w;
            }
        }
        #pragma unroll
        for (int i = 0; i < 4; i++) {
            float4 z = make_float4(fmaxf(acc[i].x, 0.f), fmaxf(acc[i].y, 0.f),
                                   fmaxf(acc[i].z, 0.f), fmaxf(acc[i].w, 0.f));
            *reinterpret_cast<float4*>(&sz[(lnb + i) * H + j0]) = z;
        }
    }
    __syncwarp();

    // Phase B
    {
        float4 au[4], ar[4];
        float4 b2 = *reinterpret_cast<const float4*>(&sb2[j0]);
        #pragma unroll
        for (int i = 0; i < 4; i++) {
            au[i] = make_float4(0.f, 0.f, 0.f, 0.f);
            ar[i] = b2;
        }
        #pragma unroll 4
        for (int k = 0; k < H; k++) {
            float4 wl = *reinterpret_cast<const float4*>(&sW2l[k * H + j0]);
            float4 wr = *reinterpret_cast<const float4*>(&sW2r[k * H + j0]);
            #pragma unroll
            for (int i = 0; i < 4; i++) {
                float zv = sz[(lnb + i) * H + k];
                au[i].x += zv * wl.x; au[i].y += zv * wl.y;
                au[i].z += zv * wl.z; au[i].w += zv * wl.w;
                ar[i].x += zv * wr.x; ar[i].y += zv * wr.y;
                ar[i].z += zv * wr.z; ar[i].w += zv * wr.w;
            }
        }
        #pragma unroll
        for (int i = 0; i < 4; i++) {
            int node = nodeb + i;
            if (node < N_NODES) {
                __half2 h01 = __floats2half2_rn(au[i].x, au[i].y);
                __half2 h23 = __floats2half2_rn(au[i].z, au[i].w);
                uint2 us;
                us.x = *reinterpret_cast<unsigned*>(&h01);
                us.y = *reinterpret_cast<unsigned*>(&h23);
                reinterpret_cast<uint2*>(g_uh)[(size_t)node * 16 + j4] = us;
                reinterpret_cast<float4*>(g_yr)[(size_t)node * 16 + j4] = ar[i];
            }
        }
    }
}

// ---- Layer 2 aggregation (R13 proven uint2 form), epilogue fused -----------

__device__ __forceinline__ void acc4(uint2 u, float& a0, float& a1, float& a2, float& a3) {
    __half2 hx = *reinterpret_cast<__half2*>(&u.x);
    __half2 hy = *reinterpret_cast<__half2*>(&u.y);
    float2 fx = __half22float2(hx);
    float2 fy = __half22float2(hy);
    a0 += fx.x; a1 += fx.y; a2 += fy.x; a3 += fy.y;
}

__global__ void k_agg2(float* __restrict__ out) {
    int t = threadIdx.x;              // 256 = 8 warps = 8 nodes
    int node = blockIdx.x * 8 + (t >> 5);   // N_NODES % 8 == 0
    int lane = t & 31;
    int half = lane >> 4;
    int sub  = lane & 15;

    int beg = g_rowstart[node];
    int end = g_rowstart[node + 1];
    int deg = end - beg;

    float a0 = 0, a1 = 0, a2 = 0, a3 = 0;
    const uint2* uh = reinterpret_cast<const uint2*>(g_uh);
    for (int base = beg; base < end; base += 32) {
        int idx = base + lane;
        int sidx = (idx < end) ? __ldg(&g_adj[idx]) : 0;
        int m = end - base; if (m > 32) m = 32;
        int j = 0;
        for (; j + 16 <= m; j += 16) {
            int p0 = __shfl_sync(0xffffffffu, sidx, j + 0  + half);
            int p1 = __shfl_sync(0xffffffffu, sidx, j + 2  + half);
            int p2 = __shfl_sync(0xffffffffu, sidx, j + 4  + half);
            int p3 = __shfl_sync(0xffffffffu, sidx, j + 6  + half);
            int p4 = __shfl_sync(0xffffffffu, sidx, j + 8  + half);
            int p5 = __shfl_sync(0xffffffffu, sidx, j + 10 + half);
            int p6 = __shfl_sync(0xffffffffu, sidx, j + 12 + half);
            int p7 = __shfl_sync(0xffffffffu, sidx, j + 14 + half);
            uint2 u0 = __ldg(&uh[(size_t)p0 * 16 + sub]);
            uint2 u1 = __ldg(&uh[(size_t)p1 * 16 + sub]);
            uint2 u2 = __ldg(&uh[(size_t)p2 * 16 + sub]);
            uint2 u3 = __ldg(&uh[(size_t)p3 * 16 + sub]);
            uint2 u4 = __ldg(&uh[(size_t)p4 * 16 + sub]);
            uint2 u5 = __ldg(&uh[(size_t)p5 * 16 + sub]);
            uint2 u6 = __ldg(&uh[(size_t)p6 * 16 + sub]);
            uint2 u7 = __ldg(&uh[(size_t)p7 * 16 + sub]);
            acc4(u0, a0, a1, a2, a3); acc4(u1, a0, a1, a2, a3);
            acc4(u2, a0, a1, a2, a3); acc4(u3, a0, a1, a2, a3);
            acc4(u4, a0, a1, a2, a3); acc4(u5, a0, a1, a2, a3);
            acc4(u6, a0, a1, a2, a3); acc4(u7, a0, a1, a2, a3);
        }
        for (; j + 8 <= m; j += 8) {
            int p0 = __shfl_sync(0xffffffffu, sidx, j + 0 + half);
            int p1 = __shfl_sync(0xffffffffu, sidx, j + 2 + half);
            int p2 = __shfl_sync(0xffffffffu, sidx, j + 4 + half);
            int p3 = __shfl_sync(0xffffffffu, sidx, j + 6 + half);
            uint2 u0 = __ldg(&uh[(size_t)p0 * 16 + sub]);
            uint2 u1 = __ldg(&uh[(size_t)p1 * 16 + sub]);
            uint2 u2 = __ldg(&uh[(size_t)p2 * 16 + sub]);
            uint2 u3 = __ldg(&uh[(size_t)p3 * 16 + sub]);
            acc4(u0, a0, a1, a2, a3); acc4(u1, a0, a1, a2, a3);
            acc4(u2, a0, a1, a2, a3); acc4(u3, a0, a1, a2, a3);
        }
        for (; j + 2 <= m; j += 2) {
            int p = __shfl_sync(0xffffffffu, sidx, j + half);
            uint2 u = __ldg(&uh[(size_t)p * 16 + sub]);
            acc4(u, a0, a1, a2, a3);
        }
        if (j < m) {
            int p = __shfl_sync(0xffffffffu, sidx, j);
            if (half == 0) {
                uint2 u = __ldg(&uh[(size_t)p * 16 + sub]);
                acc4(u, a0, a1, a2, a3);
            }
        }
    }
    a0 += __shfl_xor_sync(0xffffffffu, a0, 16);
    a1 += __shfl_xor_sync(0xffffffffu, a1, 16);
    a2 += __shfl_xor_sync(0xffffffffu, a2, 16);
    a3 += __shfl_xor_sync(0xffffffffu, a3, 16);

    if (half == 0) {
        float inv = (deg > 0) ? 1.0f / (float)deg : 0.0f;
        const float4* yr4 = reinterpret_cast<const float4*>(g_yr + (size_t)node * H);
        float4 y = __ldg(&yr4[sub]);
        float4 r = make_float4(a0 * inv + y.x, a1 * inv + y.y,
                               a2 * inv + y.z, a3 * inv + y.w);
        reinterpret_cast<float4*>(out + (size_t)node * H)[sub] = r;
    }
}

extern "C" void kernel_launch(void* const* d_in, const int* in_sizes, int n_in,
                              void* d_out, int out_size) {
    const float* x   = (const float*)d_in[0];
    const int*   ei  = (const int*)d_in[1];
    const float* W1l = (const float*)d_in[2];
    const float* b1l = (const float*)d_in[3];
    const float* W1r = (const float*)d_in[4];
    const float* W2l = (const float*)d_in[5];
    const float* b2l = (const float*)d_in[6];
    const float* W2r = (const float*)d_in[7];
    float* out = (float*)d_out;

    // CSR build: RED-only count, scan (+cursor), cursor-atomic place
    k_count <<<(E4 + 255) / 256, 256>>>(ei);
    k_scan1 <<<SCAN_BLOCKS, 256>>>();
    k_scan23<<<SCAN_BLOCKS, 256>>>();
    k_place <<<(E4 + 255) / 256, 256>>>(ei);
    // fused layer-1 aggregation + node transform
    k_node<<<(N_NODES + NB - 1) / NB, 256>>>(x, W1l, b1l, W1r, W2l, b2l, W2r);
    // layer-2 aggregation + epilogue
    k_agg2<<<N_NODES / 8, 256>>>(out);
}

// round 17
// speedup vs baseline: 1.0155x; 1.0155x over previous
#include <cuda_runtime.h>
#include <cuda_fp16.h>

#define N_NODES 50000
#define N_EDGES 1600000
#define IN_DIM 6
#define H 64
#define SCAN_BLOCKS ((N_NODES + 255) / 256)   // 196
#define NB 64                                  // nodes per k_node block
#define E4 (N_EDGES / 4)                       // 400000 int4s

// Scratch (device globals — zero-initialized at load; no runtime allocation)
__device__ int    g_deg     [N_NODES];        // reset to 0 by k_scan each replay
__device__ int    g_rowstart[N_NODES + 1];
__device__ int    g_pos     [N_EDGES];
__device__ int    g_adj     [N_EDGES];
__device__ int    g_bsum    [SCAN_BLOCKS];
__device__ int    g_ready;                    // re-armed to 0 by k_count each replay
__device__ __half g_uh      [N_NODES * H];    // u = z @ W2_l   (fp16, gather operand)
__device__ float  g_yr      [N_NODES * H];    // yr = z @ W2_r + b2_l

// ---- CSR build (R13 proven: 4 edges/thread, atomic-return count + pos) ----

__global__ void k_count(const int* __restrict__ ei) {
    int tid = blockIdx.x * blockDim.x + threadIdx.x;
    if (tid == 0) g_ready = 0;                 // re-arm the fused scan
    if (tid >= E4) return;
    const int4* dsts = reinterpret_cast<const int4*>(ei + N_EDGES);
    int4 d = __ldg(&dsts[tid]);
    int p0 = atomicAdd(&g_deg[d.x], 1);
    int p1 = atomicAdd(&g_deg[d.y], 1);
    int p2 = atomicAdd(&g_deg[d.z], 1);
    int p3 = atomicAdd(&g_deg[d.w], 1);
    reinterpret_cast<int4*>(g_pos)[tid] = make_int4(p0, p1, p2, p3);
}

__device__ __forceinline__ int warp_incl_scan(int v, int lane) {
    #pragma unroll
    for (int o = 1; o < 32; o <<= 1) {
        int u = __shfl_up_sync(0xffffffffu, v, o);
        if (lane >= o) v += u;
    }
    return v;
}

// Fused grid-cooperative scan: all 196 blocks are co-resident (196 << 1184
// wave-1 slots at 256 thr/block), so publish-then-spin is deadlock-free.
__global__ void k_scan() {
    __shared__ int ws[8];
    __shared__ int incl[256];
    int t = threadIdx.x;
    int bid = blockIdx.x;
    int lane = t & 31, w = t >> 5;

    // local exclusive scan of this block's 256 degrees
    int i = bid * 256 + t;
    int val = (i < N_NODES) ? g_deg[i] : 0;
    int v = warp_incl_scan(val, lane);
    if (lane == 31) ws[w] = v;
    __syncthreads();
    if (w == 0 && lane < 8) {
        int u = ws[lane];
        #pragma unroll
        for (int o = 1; o < 8; o <<= 1) {
            int p = __shfl_up_sync(0xffu, u, o);
            if (lane >= o) u += p;
        }
        ws[lane] = u;
    }
    __syncthreads();
    int excl = (v - val) + (w > 0 ? ws[w - 1] : 0);
    int blocksum = 0;
    if (t == 255) blocksum = excl + val;

    // publish block sum, spin until all published
    if (t == 255) {
        g_bsum[bid] = blocksum;
        __threadfence();
        atomicAdd(&g_ready, 1);
    }
    __syncthreads();
    if (t == 0) {
        volatile int* r = &g_ready;
        while (*r < SCAN_BLOCKS) { }
    }
    __syncthreads();

    // every block rescans the 196 block sums to get its own offset
    {
        volatile int* bs = g_bsum;
        int bval = (t < SCAN_BLOCKS) ? bs[t] : 0;
        int bv = warp_incl_scan(bval, lane);
        if (lane == 31) ws[w] = bv;
        __syncthreads();
        if (w == 0 && lane < 8) {
            int u = ws[lane];
            #pragma unroll
            for (int o = 1; o < 8; o <<= 1) {
                int p = __shfl_up_sync(0xffu, u, o);
                if (lane >= o) u += p;
            }
            ws[lane] = u;
        }
        __syncthreads();
        incl[t] = bv + (w > 0 ? ws[w - 1] : 0);
        __syncthreads();
    }
    int off = (bid > 0) ? incl[bid - 1] : 0;
    if (i < N_NODES) {
        g_rowstart[i] = excl + off;
        g_deg[i] = 0;
    }
    if (i == 0) g_rowstart[N_NODES] = N_EDGES;
}

// Atomic-free placement, 4 edges per thread (R13 proven)
__global__ void k_place(const int* __restrict__ ei) {
    int tid = blockIdx.x * blockDim.x + threadIdx.x;
    if (tid >= E4) return;
    const int4* srcs = reinterpret_cast<const int4*>(ei);
    const int4* dsts = reinterpret_cast<const int4*>(ei + N_EDGES);
    int4 s = __ldg(&srcs[tid]);
    int4 d = __ldg(&dsts[tid]);
    int4 p = reinterpret_cast<const int4*>(g_pos)[tid];
    int r0 = __ldg(&g_rowstart[d.x]);
    int r1 = __ldg(&g_rowstart[d.y]);
    int r2 = __ldg(&g_rowstart[d.z]);
    int r3 = __ldg(&g_rowstart[d.w]);
    g_adj[r0 + p.x] = s.x;
    g_adj[r1 + p.y] = s.y;
    g_adj[r2 + p.z] = s.z;
    g_adj[r3 + p.w] = s.w;
}

// ---- Fused node kernel (R13 proven) ----------------------------------------
__global__ void k_node(const float* __restrict__ x,
                       const float* __restrict__ W1l,
                       const float* __restrict__ b1l,
                       const float* __restrict__ W1r,
                       const float* __restrict__ W2l,
                       const float* __restrict__ b2l,
                       const float* __restrict__ W2r) {
    __shared__ __align__(16) float sW1l[IN_DIM * H];
    __shared__ __align__(16) float sW1r[IN_DIM * H];
    __shared__ __align__(16) float sb1[H];
    __shared__ __align__(16) float sW2l[H * H];
    __shared__ __align__(16) float sW2r[H * H];
    __shared__ __align__(16) float sb2[H];
    __shared__ __align__(16) float smean[NB * IN_DIM];
    __shared__ __align__(16) float sz[NB * H];
    int t = threadIdx.x;
    for (int i = t; i < IN_DIM * H; i += 256) { sW1l[i] = W1l[i]; sW1r[i] = W1r[i]; }
    for (int i = t; i < H * H; i += 256)      { sW2l[i] = W2l[i]; sW2r[i] = W2r[i]; }
    if (t < H) { sb1[t] = b1l[t]; sb2[t] = b2l[t]; }

    int base = blockIdx.x * NB;
    int w = t >> 5, lane = t & 31;

    #pragma unroll
    for (int i = 0; i < 8; i++) {
        int node = base + w * 8 + i;
        int ln = w * 8 + i;
        float a0 = 0, a1 = 0, a2 = 0, a3 = 0, a4 = 0, a5 = 0;
        int beg = 0, end = 0;
        if (node < N_NODES) {
            beg = g_rowstart[node];
            end = g_rowstart[node + 1];
            for (int p = beg + lane; p < end; p += 32) {
                int s = __ldg(&g_adj[p]);
                const float2* xs = reinterpret_cast<const float2*>(x + (size_t)s * IN_DIM);
                float2 u = __ldg(&xs[0]), q = __ldg(&xs[1]), r = __ldg(&xs[2]);
                a0 += u.x; a1 += u.y; a2 += q.x; a3 += q.y; a4 += r.x; a5 += r.y;
            }
        }
        #pragma unroll
        for (int o = 16; o > 0; o >>= 1) {
            a0 += __shfl_xor_sync(0xffffffffu, a0, o);
            a1 += __shfl_xor_sync(0xffffffffu, a1, o);
            a2 += __shfl_xor_sync(0xffffffffu, a2, o);
            a3 += __shfl_xor_sync(0xffffffffu, a3, o);
            a4 += __shfl_xor_sync(0xffffffffu, a4, o);
            a5 += __shfl_xor_sync(0xffffffffu, a5, o);
        }
        if (lane == 0 && node < N_NODES) {
            int deg = end - beg;
            float inv = (deg > 0) ? 1.0f / (float)deg : 0.0f;
            smean[ln * IN_DIM + 0] = a0 * inv;
            smean[ln * IN_DIM + 1] = a1 * inv;
            smean[ln * IN_DIM + 2] = a2 * inv;
            smean[ln * IN_DIM + 3] = a3 * inv;
            smean[ln * IN_DIM + 4] = a4 * inv;
            smean[ln * IN_DIM + 5] = a5 * inv;
        }
    }
    __syncthreads();

    int nq = t >> 4;
    int j4 = t & 15;
    int j0 = j4 * 4;
    int lnb = nq * 4;
    int nodeb = base + lnb;

    // Phase A
    {
        float4 acc[4];
        float4 b = *reinterpret_cast<const float4*>(&sb1[j0]);
        #pragma unroll
        for (int i = 0; i < 4; i++) acc[i] = b;
        #pragma unroll
        for (int k = 0; k < IN_DIM; k++) {
            float4 wl = *reinterpret_cast<const float4*>(&sW1l[k * H + j0]);
            float4 wr = *reinterpret_cast<const float4*>(&sW1r[k * H + j0]);
            #pragma unroll
            for (int i = 0; i < 4; i++) {
                int node = nodeb + i;
                float m = smean[(lnb + i) * IN_DIM + k];
                float xv = (node < N_NODES) ? __ldg(&x[(size_t)node * IN_DIM + k]) : 0.0f;
                acc[i].x += m * wl.x + xv * wr.x;
                acc[i].y += m * wl.y + xv * wr.y;
                acc[i].z += m * wl.z + xv * wr.z;
                acc[i].w += m * wl.w + xv * wr.w;
            }
        }
        #pragma unroll
        for (int i = 0; i < 4; i++) {
            float4 z = make_float4(fmaxf(acc[i].x, 0.f), fmaxf(acc[i].y, 0.f),
                                   fmaxf(acc[i].z, 0.f), fmaxf(acc[i].w, 0.f));
            *reinterpret_cast<float4*>(&sz[(lnb + i) * H + j0]) = z;
        }
    }
    __syncwarp();

    // Phase B
    {
        float4 au[4], ar[4];
        float4 b2 = *reinterpret_cast<const float4*>(&sb2[j0]);
        #pragma unroll
        for (int i = 0; i < 4; i++) {
            au[i] = make_float4(0.f, 0.f, 0.f, 0.f);
            ar[i] = b2;
        }
        #pragma unroll 4
        for (int k = 0; k < H; k++) {
            float4 wl = *reinterpret_cast<const float4*>(&sW2l[k * H + j0]);
            float4 wr = *reinterpret_cast<const float4*>(&sW2r[k * H + j0]);
            #pragma unroll
            for (int i = 0; i < 4; i++) {
                float zv = sz[(lnb + i) * H + k];
                au[i].x += zv * wl.x; au[i].y += zv * wl.y;
                au[i].z += zv * wl.z; au[i].w += zv * wl.w;
                ar[i].x += zv * wr.x; ar[i].y += zv * wr.y;
                ar[i].z += zv * wr.z; ar[i].w += zv * wr.w;
            }
        }
        #pragma unroll
        for (int i = 0; i < 4; i++) {
            int node = nodeb + i;
            if (node < N_NODES) {
                __half2 h01 = __floats2half2_rn(au[i].x, au[i].y);
                __half2 h23 = __floats2half2_rn(au[i].z, au[i].w);
                uint2 us;
                us.x = *reinterpret_cast<unsigned*>(&h01);
                us.y = *reinterpret_cast<unsigned*>(&h23);
                reinterpret_cast<uint2*>(g_uh)[(size_t)node * 16 + j4] = us;
                reinterpret_cast<float4*>(g_yr)[(size_t)node * 16 + j4] = ar[i];
            }
        }
    }
}

// ---- Layer 2 aggregation (R13 proven uint2 form), epilogue fused -----------

__device__ __forceinline__ void acc4(uint2 u, float& a0, float& a1, float& a2, float& a3) {
    __half2 hx = *reinterpret_cast<__half2*>(&u.x);
    __half2 hy = *reinterpret_cast<__half2*>(&u.y);
    float2 fx = __half22float2(hx);
    float2 fy = __half22float2(hy);
    a0 += fx.x; a1 += fx.y; a2 += fy.x; a3 += fy.y;
}

__global__ void k_agg2(float* __restrict__ out) {
    int t = threadIdx.x;              // 256 = 8 warps = 8 nodes
    int node = blockIdx.x * 8 + (t >> 5);   // N_NODES % 8 == 0
    int lane = t & 31;
    int half = lane >> 4;
    int sub  = lane & 15;

    int beg = g_rowstart[node];
    int end = g_rowstart[node + 1];
    int deg = end - beg;

    float a0 = 0, a1 = 0, a2 = 0, a3 = 0;
    const uint2* uh = reinterpret_cast<const uint2*>(g_uh);
    for (int base = beg; base < end; base += 32) {
        int idx = base + lane;
        int sidx = (idx < end) ? __ldg(&g_adj[idx]) : 0;
        int m = end - base; if (m > 32) m = 32;
        int j = 0;
        for (; j + 16 <= m; j += 16) {
            int p0 = __shfl_sync(0xffffffffu, sidx, j + 0  + half);
            int p1 = __shfl_sync(0xffffffffu, sidx, j + 2  + half);
            int p2 = __shfl_sync(0xffffffffu, sidx, j + 4  + half);
            int p3 = __shfl_sync(0xffffffffu, sidx, j + 6  + half);
            int p4 = __shfl_sync(0xffffffffu, sidx, j + 8  + half);
            int p5 = __shfl_sync(0xffffffffu, sidx, j + 10 + half);
            int p6 = __shfl_sync(0xffffffffu, sidx, j + 12 + half);
            int p7 = __shfl_sync(0xffffffffu, sidx, j + 14 + half);
            uint2 u0 = __ldg(&uh[(size_t)p0 * 16 + sub]);
            uint2 u1 = __ldg(&uh[(size_t)p1 * 16 + sub]);
            uint2 u2 = __ldg(&uh[(size_t)p2 * 16 + sub]);
            uint2 u3 = __ldg(&uh[(size_t)p3 * 16 + sub]);
            uint2 u4 = __ldg(&uh[(size_t)p4 * 16 + sub]);
            uint2 u5 = __ldg(&uh[(size_t)p5 * 16 + sub]);
            uint2 u6 = __ldg(&uh[(size_t)p6 * 16 + sub]);
            uint2 u7 = __ldg(&uh[(size_t)p7 * 16 + sub]);
            acc4(u0, a0, a1, a2, a3); acc4(u1, a0, a1, a2, a3);
            acc4(u2, a0, a1, a2, a3); acc4(u3, a0, a1, a2, a3);
            acc4(u4, a0, a1, a2, a3); acc4(u5, a0, a1, a2, a3);
            acc4(u6, a0, a1, a2, a3); acc4(u7, a0, a1, a2, a3);
        }
        for (; j + 8 <= m; j += 8) {
            int p0 = __shfl_sync(0xffffffffu, sidx, j + 0 + half);
            int p1 = __shfl_sync(0xffffffffu, sidx, j + 2 + half);
            int p2 = __shfl_sync(0xffffffffu, sidx, j + 4 + half);
            int p3 = __shfl_sync(0xffffffffu, sidx, j + 6 + half);
            uint2 u0 = __ldg(&uh[(size_t)p0 * 16 + sub]);
            uint2 u1 = __ldg(&uh[(size_t)p1 * 16 + sub]);
            uint2 u2 = __ldg(&uh[(size_t)p2 * 16 + sub]);
            uint2 u3 = __ldg(&uh[(size_t)p3 * 16 + sub]);
            acc4(u0, a0, a1, a2, a3); acc4(u1, a0, a1, a2, a3);
            acc4(u2, a0, a1, a2, a3); acc4(u3, a0, a1, a2, a3);
        }
        for (; j + 2 <= m; j += 2) {
            int p = __shfl_sync(0xffffffffu, sidx, j + half);
            uint2 u = __ldg(&uh[(size_t)p * 16 + sub]);
            acc4(u, a0, a1, a2, a3);
        }
        if (j < m) {
            int p = __shfl_sync(0xffffffffu, sidx, j);
            if (half == 0) {
                uint2 u = __ldg(&uh[(size_t)p * 16 + sub]);
                acc4(u, a0, a1, a2, a3);
            }
        }
    }
    a0 += __shfl_xor_sync(0xffffffffu, a0, 16);
    a1 += __shfl_xor_sync(0xffffffffu, a1, 16);
    a2 += __shfl_xor_sync(0xffffffffu, a2, 16);
    a3 += __shfl_xor_sync(0xffffffffu, a3, 16);

    if (half == 0) {
        float inv = (deg > 0) ? 1.0f / (float)deg : 0.0f;
        const float4* yr4 = reinterpret_cast<const float4*>(g_yr + (size_t)node * H);
        float4 y = __ldg(&yr4[sub]);
        float4 r = make_float4(a0 * inv + y.x, a1 * inv + y.y,
                               a2 * inv + y.z, a3 * inv + y.w);
        reinterpret_cast<float4*>(out + (size_t)node * H)[sub] = r;
    }
}

extern "C" void kernel_launch(void* const* d_in, const int* in_sizes, int n_in,
                              void* d_out, int out_size) {
    const float* x   = (const float*)d_in[0];
    const int*   ei  = (const int*)d_in[1];
    const float* W1l = (const float*)d_in[2];
    const float* b1l = (const float*)d_in[3];
    const float* W1r = (const float*)d_in[4];
    const float* W2l = (const float*)d_in[5];
    const float* b2l = (const float*)d_in[6];
    const float* W2r = (const float*)d_in[7];
    float* out = (float*)d_out;

    // CSR build: R13 count/place + single fused grid-cooperative scan
    k_count<<<(E4 + 255) / 256, 256>>>(ei);
    k_scan <<<SCAN_BLOCKS, 256>>>();
    k_place<<<(E4 + 255) / 256, 256>>>(ei);
    // fused layer-1 aggregation + node transform
    k_node<<<(N_NODES + NB - 1) / NB, 256>>>(x, W1l, b1l, W1r, W2l, b2l, W2r);
    // layer-2 aggregation + epilogue
    k_agg2<<<N_NODES / 8, 256>>>(out);
}